// round 14
// baseline (speedup 1.0000x reference)
#include <cuda_runtime.h>

#define NP 800000
#define EPS 1e-5f
typedef unsigned long long u64;

// ---------------- global scratch ----------------
__device__ __align__(16) float g_h1[(size_t)NP * 64];    // stage-1 POST bn+relu
__device__ __align__(16) float g_Y2[(size_t)NP * 64];    // conv pre-BN (raw)
__device__ __align__(16) int2  g_list[8][NP];            // per-offset compacted (out, src)
__device__ __align__(16) int   g_cnt[8];
__device__ __align__(16) float g_stats[128];             // Y2: sum[0,64) sq[64,128)
__device__ __align__(16) float g_C[4096];                // 64x64 second-moment (raw sums)
__device__ __align__(16) float g_Csum[64];               // column sums
// scale/shift: Y1 @0..64, YS @64..320, h2 @320..384, Y3 @384..640
__device__ __align__(16) float g_scale[640];
__device__ __align__(16) float g_shift[640];

// ---------------- f32x2 helpers ----------------
__device__ __forceinline__ void ffma2(u64 &acc, u64 x, u64 w) {
    asm("fma.rn.f32x2 %0, %1, %2, %0;" : "+l"(acc) : "l"(x), "l"(w));
}
__device__ __forceinline__ u64 pack2(float a, float b) {
    u64 r; asm("mov.b64 %0, {%1, %2};" : "=l"(r)
               : "r"(__float_as_uint(a)), "r"(__float_as_uint(b))); return r;
}
__device__ __forceinline__ u64 dup2(float v) {
    u64 r; asm("mov.b64 %0, {%1, %1};" : "=l"(r) : "r"(__float_as_uint(v))); return r;
}
__device__ __forceinline__ float2 unpack2(u64 v) {
    unsigned lo, hi; asm("mov.b64 {%0, %1}, %2;" : "=r"(lo), "=r"(hi) : "l"(v));
    return make_float2(__uint_as_float(lo), __uint_as_float(hi));
}
__device__ __forceinline__ void load_row(const float* __restrict__ row, u64* xp) {
    const ulonglong2* xr = (const ulonglong2*)row;
#pragma unroll
    for (int m = 0; m < 16; m++) { ulonglong2 v = xr[m]; xp[2*m] = v.x; xp[2*m+1] = v.y; }
}

// ---- dot2x4: 2 weight columns x 4 rows. Per m: 2 broadcast LDS.128 : 16 FFMA2 (1:1 wf:fma) ----
__device__ __forceinline__ void dot2x4(const float* __restrict__ WT,
        const u64* __restrict__ x0, const u64* __restrict__ x1,
        const u64* __restrict__ x2, const u64* __restrict__ x3, int c,
        float2& r0, float2& r1, float2& r2, float2& r3) {
    const ulonglong2* wA = (const ulonglong2*)(WT + (c + 0) * 64);
    const ulonglong2* wB = (const ulonglong2*)(WT + (c + 1) * 64);
    u64 a0 = 0, a1 = 0, a2 = 0, a3 = 0;
    u64 b0 = 0, b1 = 0, b2 = 0, b3 = 0;
#pragma unroll
    for (int m = 0; m < 16; m++) {
        ulonglong2 vA = wA[m];
        ffma2(a0, x0[2*m], vA.x); ffma2(a0, x0[2*m+1], vA.y);
        ffma2(a1, x1[2*m], vA.x); ffma2(a1, x1[2*m+1], vA.y);
        ffma2(a2, x2[2*m], vA.x); ffma2(a2, x2[2*m+1], vA.y);
        ffma2(a3, x3[2*m], vA.x); ffma2(a3, x3[2*m+1], vA.y);
        ulonglong2 vB = wB[m];
        ffma2(b0, x0[2*m], vB.x); ffma2(b0, x0[2*m+1], vB.y);
        ffma2(b1, x1[2*m], vB.x); ffma2(b1, x1[2*m+1], vB.y);
        ffma2(b2, x2[2*m], vB.x); ffma2(b2, x2[2*m+1], vB.y);
        ffma2(b3, x3[2*m], vB.x); ffma2(b3, x3[2*m+1], vB.y);
    }
    float2 p, q;
    p = unpack2(a0); q = unpack2(b0); r0 = make_float2(p.x + p.y, q.x + q.y);
    p = unpack2(a1); q = unpack2(b1); r1 = make_float2(p.x + p.y, q.x + q.y);
    p = unpack2(a2); q = unpack2(b2); r2 = make_float2(p.x + p.y, q.x + q.y);
    p = unpack2(a3); q = unpack2(b3); r3 = make_float2(p.x + p.y, q.x + q.y);
}

__global__ void zero_kernel(int mode) {
    int i = blockIdx.x * blockDim.x + threadIdx.x;
    if (i < 4096) g_C[i] = 0.f;
    if (i < 64) g_Csum[i] = 0.f;
    if (mode == 0) {
        if (i < 128) g_stats[i] = 0.f;
        if (i < 8) g_cnt[i] = 0;
    }
}

// ---------------- SYRK: C += X^T X, Csum += colsums(X) ----------------
__global__ __launch_bounds__(256) void syrk_kernel(const float* __restrict__ Xin, int which) {
    __shared__ float tile[32 * 64];
    __shared__ float sc[64], sh[64];
    int t = threadIdx.x;
    if (which && t < 64) { sc[t] = g_scale[320 + t]; sh[t] = g_shift[320 + t]; }
    int ta = t >> 4, tb = t & 15;
    u64 acc[8] = {0,0,0,0,0,0,0,0};
    float cs0 = 0.f, cs1 = 0.f, cs2 = 0.f, cs3 = 0.f;
    const float4* src = (const float4*)(which ? (const float*)g_Y2 : Xin);
    long base16 = (long)blockIdx.x * 3200 * 16;

    for (int t0 = 0; t0 < 3200; t0 += 32) {
        __syncthreads();
        for (int i = t; i < 512; i += 256) {
            float4 v = src[base16 + (long)t0 * 16 + i];
            if (which) {
                int c0 = (i & 15) * 4;
                float4 s = *(const float4*)(sc + c0);
                float4 h = *(const float4*)(sh + c0);
                v.x = fmaxf(fmaf(v.x, s.x, h.x), 0.f);
                v.y = fmaxf(fmaf(v.y, s.y, h.y), 0.f);
                v.z = fmaxf(fmaf(v.z, s.z, h.z), 0.f);
                v.w = fmaxf(fmaf(v.w, s.w, h.w), 0.f);
            }
            *(float4*)(tile + i * 4) = v;
        }
        __syncthreads();
#pragma unroll 4
        for (int r = 0; r < 32; r++) {
            float4 xa = *(const float4*)(tile + r * 64 + ta * 4);
            float4 xb = *(const float4*)(tile + r * 64 + tb * 4);
            u64 b01 = pack2(xb.x, xb.y), b23 = pack2(xb.z, xb.w);
            u64 d;
            d = dup2(xa.x); ffma2(acc[0], d, b01); ffma2(acc[1], d, b23);
            d = dup2(xa.y); ffma2(acc[2], d, b01); ffma2(acc[3], d, b23);
            d = dup2(xa.z); ffma2(acc[4], d, b01); ffma2(acc[5], d, b23);
            d = dup2(xa.w); ffma2(acc[6], d, b01); ffma2(acc[7], d, b23);
            if (tb == 0) { cs0 += xa.x; cs1 += xa.y; cs2 += xa.z; cs3 += xa.w; }
        }
    }
#pragma unroll
    for (int a = 0; a < 4; a++) {
        float2 p0 = unpack2(acc[a * 2]), p1 = unpack2(acc[a * 2 + 1]);
        int row = ta * 4 + a;
        atomicAdd(&g_C[row * 64 + tb * 4 + 0], p0.x);
        atomicAdd(&g_C[row * 64 + tb * 4 + 1], p0.y);
        atomicAdd(&g_C[row * 64 + tb * 4 + 2], p1.x);
        atomicAdd(&g_C[row * 64 + tb * 4 + 3], p1.y);
    }
    if (tb == 0) {
        atomicAdd(&g_Csum[ta * 4 + 0], cs0);
        atomicAdd(&g_Csum[ta * 4 + 1], cs1);
        atomicAdd(&g_Csum[ta * 4 + 2], cs2);
        atomicAdd(&g_Csum[ta * 4 + 3], cs3);
    }
}

// ---------------- analytic BN params for y = x@W + b ----------------
__device__ __forceinline__ void prep_body(const float* __restrict__ W,
        const float* __restrict__ gamma, const float* __restrict__ beta,
        int ncols, int outOff) {
    __shared__ float Cs[4096];
    __shared__ float m[64];
    int t = threadIdx.x;
    float invN = 1.0f / (float)NP;
    for (int i = t; i < 4096; i += blockDim.x) Cs[i] = g_C[i] * invN;
    if (t < 64) m[t] = g_Csum[t] * invN;
    __syncthreads();
    if (t < ncols) {
        float w[64];
#pragma unroll
        for (int a = 0; a < 64; a++) w[a] = W[a * ncols + t];
        float mu = 0.f;
#pragma unroll
        for (int a = 0; a < 64; a++) mu = fmaf(m[a], w[a], mu);
        float q = 0.f;
#pragma unroll
        for (int a = 0; a < 64; a++) {
            const float* Cr = Cs + a * 64;
            float d0 = 0.f, d1 = 0.f, d2 = 0.f, d3 = 0.f;
#pragma unroll
            for (int b = 0; b < 64; b += 4) {
                d0 = fmaf(Cr[b + 0], w[b + 0], d0);
                d1 = fmaf(Cr[b + 1], w[b + 1], d1);
                d2 = fmaf(Cr[b + 2], w[b + 2], d2);
                d3 = fmaf(Cr[b + 3], w[b + 3], d3);
            }
            q = fmaf(w[a], (d0 + d1) + (d2 + d3), q);
        }
        float var = q - mu * mu;
        float scv = rsqrtf(var + EPS) * gamma[t];
        g_scale[outOff + t] = scv;
        g_shift[outOff + t] = beta[t] - mu * scv;
    }
}
__global__ void prep_dual_kernel(const float* __restrict__ w1, const float* __restrict__ g1,
                                 const float* __restrict__ be1,
                                 const float* __restrict__ ws, const float* __restrict__ gs,
                                 const float* __restrict__ bes) {
    if (blockIdx.x == 0) prep_body(w1, g1, be1, 64, 0);
    else                 prep_body(ws, gs, bes, 256, 64);
}
__global__ void prep_kernel(const float* __restrict__ W, const float* __restrict__ gamma,
                            const float* __restrict__ beta, int ncols, int outOff) {
    prep_body(W, gamma, beta, ncols, outOff);
}

// ---------------- GEMM1 (4 rows/thread): h1 = relu(bn(feats@w1)); out = bn(feats@ws) ----------------
__global__ __launch_bounds__(256, 1) void gemm1_kernel(
    const float* __restrict__ feats, const float* __restrict__ w1,
    const float* __restrict__ ws, float* __restrict__ outYS) {
    extern __shared__ float sm[];
    float* WT = sm;               // 320 cols x 64 (transposed)
    float* scA = sm + 20480;      // 320
    float* shA = sm + 20800;      // 320
    int t = threadIdx.x;
    for (int i = t; i < 20480; i += 256) {
        int c = i >> 6, j = i & 63;
        WT[i] = (c < 64) ? w1[j * 64 + c] : ws[j * 256 + (c - 64)];
    }
    for (int i = t; i < 320; i += 256) { scA[i] = g_scale[i]; shA[i] = g_shift[i]; }
    __syncthreads();

    int q = blockIdx.x * 256 + t;
    if (q >= 200000) return;
    long r0 = 4L * q;
    u64 x0[32], x1[32], x2[32], x3[32];
    load_row(feats + (r0 + 0) * 64, x0);
    load_row(feats + (r0 + 1) * 64, x1);
    load_row(feats + (r0 + 2) * 64, x2);
    load_row(feats + (r0 + 3) * 64, x3);
    float* h1p = g_h1 + r0 * 64;
    float* ysp = outYS + r0 * 256 - 64;
#pragma unroll 1
    for (int c = 0; c < 320; c += 2) {
        float2 v0, v1, v2, v3;
        dot2x4(WT, x0, x1, x2, x3, c, v0, v1, v2, v3);
        float sx = scA[c], sy = scA[c + 1];
        float hx = shA[c], hy = shA[c + 1];
        v0.x = fmaf(v0.x, sx, hx); v0.y = fmaf(v0.y, sy, hy);
        v1.x = fmaf(v1.x, sx, hx); v1.y = fmaf(v1.y, sy, hy);
        v2.x = fmaf(v2.x, sx, hx); v2.y = fmaf(v2.y, sy, hy);
        v3.x = fmaf(v3.x, sx, hx); v3.y = fmaf(v3.y, sy, hy);
        if (c < 64) {
            *(u64*)(h1p + 0 * 64 + c) = pack2(fmaxf(v0.x, 0.f), fmaxf(v0.y, 0.f));
            *(u64*)(h1p + 1 * 64 + c) = pack2(fmaxf(v1.x, 0.f), fmaxf(v1.y, 0.f));
            *(u64*)(h1p + 2 * 64 + c) = pack2(fmaxf(v2.x, 0.f), fmaxf(v2.y, 0.f));
            *(u64*)(h1p + 3 * 64 + c) = pack2(fmaxf(v3.x, 0.f), fmaxf(v3.y, 0.f));
        } else {
            *(u64*)(ysp + 0 * 256 + c) = pack2(v0.x, v0.y);
            *(u64*)(ysp + 1 * 256 + c) = pack2(v1.x, v1.y);
            *(u64*)(ysp + 2 * 256 + c) = pack2(v2.x, v2.y);
            *(u64*)(ysp + 3 * 256 + c) = pack2(v3.x, v3.y);
        }
    }
}

// ---------------- direct column stats for Y2 ----------------
__global__ __launch_bounds__(256) void stats2_kernel() {
    __shared__ float s[128];
    int t = threadIdx.x;
    for (int i = t; i < 128; i += 256) s[i] = 0.f;
    __syncthreads();
    int cg = t & 15;
    long r = (long)blockIdx.x * 16 + (t >> 4);
    long stride = (long)gridDim.x * 16;
    float s0=0,s1=0,s2=0,s3=0,q0=0,q1=0,q2=0,q3=0;
    for (; r < NP; r += stride) {
        float4 v = *(const float4*)(g_Y2 + r * 64 + cg * 4);
        s0 += v.x; q0 = fmaf(v.x, v.x, q0);
        s1 += v.y; q1 = fmaf(v.y, v.y, q1);
        s2 += v.z; q2 = fmaf(v.z, v.z, q2);
        s3 += v.w; q3 = fmaf(v.w, v.w, q3);
    }
    int c = cg * 4;
    atomicAdd(&s[c+0], s0); atomicAdd(&s[c+1], s1);
    atomicAdd(&s[c+2], s2); atomicAdd(&s[c+3], s3);
    atomicAdd(&s[64+c+0], q0); atomicAdd(&s[64+c+1], q1);
    atomicAdd(&s[64+c+2], q2); atomicAdd(&s[64+c+3], q3);
    __syncthreads();
    for (int i = t; i < 128; i += 256) atomicAdd(&g_stats[i], s[i]);
}
__global__ void finalize2_kernel(const float* __restrict__ gamma, const float* __restrict__ beta) {
    int t = threadIdx.x;
    if (t < 64) {
        float inv = 1.0f / (float)NP;
        float m = g_stats[t] * inv;
        float v = g_stats[64 + t] * inv - m * m;
        float sc = rsqrtf(v + EPS) * gamma[t];
        g_scale[320 + t] = sc;
        g_shift[320 + t] = beta[t] - m * sc;
    }
}

// ---------------- compaction ----------------
__global__ __launch_bounds__(256) void compact_kernel(const int* __restrict__ nbrs) {
    __shared__ int scnt[8], sbase[8], woff[8][8];
    int t = threadIdx.x, w = t >> 5, lane = t & 31;
    if (t < 8) scnt[t] = 0;
    __syncthreads();
    int i = blockIdx.x * 256 + t;
    int nb[8];
    {
        int kk = 0;
#pragma unroll
        for (int k = 0; k < 9; k++) {
            if (k == 4) continue;
            nb[kk++] = nbrs[i * 9 + k];
        }
    }
    unsigned ball[8];
#pragma unroll
    for (int k = 0; k < 8; k++) {
        unsigned m = __ballot_sync(0xffffffffu, nb[k] >= 0);
        ball[k] = m;
        if (lane == 0) woff[k][w] = atomicAdd(&scnt[k], __popc(m));
    }
    __syncthreads();
    if (t < 8) sbase[t] = atomicAdd(&g_cnt[t], scnt[t]);
    __syncthreads();
#pragma unroll
    for (int k = 0; k < 8; k++) {
        if (nb[k] >= 0) {
            int r = __popc(ball[k] & ((1u << lane) - 1u));
            g_list[k][sbase[k] + woff[k][w] + r] = make_int2(i, nb[k]);
        }
    }
}

// ---------------- conv center tap (4 rows/thread): Y2 = b2 + h1 @ w2[4] ----------------
__global__ __launch_bounds__(256, 1) void conv_center_kernel(
    const float* __restrict__ w2, const float* __restrict__ b2) {
    extern __shared__ float sm[];
    float* WT = sm;            // 64x64 transposed
    float* bias = sm + 4096;   // 64
    int t = threadIdx.x;
    for (int i = t; i < 4096; i += 256) {
        int c = i >> 6, j = i & 63;
        WT[i] = w2[4 * 4096 + j * 64 + c];
    }
    if (t < 64) bias[t] = b2[t];
    __syncthreads();

    int q = blockIdx.x * 256 + t;
    if (q >= 200000) return;
    long r0 = 4L * q;
    u64 x0[32], x1[32], x2[32], x3[32];
    load_row(g_h1 + (r0 + 0) * 64, x0);
    load_row(g_h1 + (r0 + 1) * 64, x1);
    load_row(g_h1 + (r0 + 2) * 64, x2);
    load_row(g_h1 + (r0 + 3) * 64, x3);
    float* yp = g_Y2 + r0 * 64;
#pragma unroll 1
    for (int c = 0; c < 64; c += 2) {
        float2 v0, v1, v2, v3;
        dot2x4(WT, x0, x1, x2, x3, c, v0, v1, v2, v3);
        float bx = bias[c], by = bias[c + 1];
        *(u64*)(yp + 0 * 64 + c) = pack2(v0.x + bx, v0.y + by);
        *(u64*)(yp + 1 * 64 + c) = pack2(v1.x + bx, v1.y + by);
        *(u64*)(yp + 2 * 64 + c) = pack2(v2.x + bx, v2.y + by);
        *(u64*)(yp + 3 * 64 + c) = pack2(v3.x + bx, v3.y + by);
    }
}

// ---------------- conv non-center tap kk (4 entries/thread) ----------------
__global__ __launch_bounds__(256, 1) void convk_kernel(const float* __restrict__ w2, int kk) {
    extern __shared__ float sm[];
    float* WT = sm;
    int tap = (kk < 4) ? kk : kk + 1;
    int t = threadIdx.x;
    for (int i = t; i < 4096; i += 256) {
        int c = i >> 6, j = i & 63;
        WT[i] = w2[tap * 4096 + j * 64 + c];
    }
    __syncthreads();

    int n = g_cnt[kk];
    for (long e = ((long)blockIdx.x * 256 + t) * 4; e < n; e += (long)gridDim.x * 1024) {
        long e1 = (e + 1 < n) ? e + 1 : e;
        long e2 = (e + 2 < n) ? e + 2 : e;
        long e3 = (e + 3 < n) ? e + 3 : e;
        int2 q0 = g_list[kk][e];
        int2 q1 = g_list[kk][e1];
        int2 q2 = g_list[kk][e2];
        int2 q3 = g_list[kk][e3];
        u64 x0[32], x1[32], x2[32], x3[32];
        load_row(g_h1 + (long)q0.y * 64, x0);
        load_row(g_h1 + (long)q1.y * 64, x1);
        load_row(g_h1 + (long)q2.y * 64, x2);
        load_row(g_h1 + (long)q3.y * 64, x3);
        float* y0 = g_Y2 + (long)q0.x * 64;
        float* y1 = g_Y2 + (long)q1.x * 64;
        float* y2 = g_Y2 + (long)q2.x * 64;
        float* y3 = g_Y2 + (long)q3.x * 64;
        bool v1g = (e + 1 < n), v2g = (e + 2 < n), v3g = (e + 3 < n);
#pragma unroll 1
        for (int c = 0; c < 64; c += 2) {
            float2 r0, r1, r2, r3;
            dot2x4(WT, x0, x1, x2, x3, c, r0, r1, r2, r3);
            float2 o;
            o = unpack2(*(u64*)(y0 + c));
            *(u64*)(y0 + c) = pack2(o.x + r0.x, o.y + r0.y);
            if (v1g) {
                o = unpack2(*(u64*)(y1 + c));
                *(u64*)(y1 + c) = pack2(o.x + r1.x, o.y + r1.y);
            }
            if (v2g) {
                o = unpack2(*(u64*)(y2 + c));
                *(u64*)(y2 + c) = pack2(o.x + r2.x, o.y + r2.y);
            }
            if (v3g) {
                o = unpack2(*(u64*)(y3 + c));
                *(u64*)(y3 + c) = pack2(o.x + r3.x, o.y + r3.y);
            }
        }
    }
}

// ---------------- GEMM3+final (4 rows/thread): out += relu(bn(bnrelu(Y2) @ w3)) ----------------
__global__ __launch_bounds__(256, 1) void gemm3_kernel(
    const float* __restrict__ w3, float* __restrict__ out) {
    extern __shared__ float sm[];
    float* WT  = sm;              // 256 cols x 64 transposed
    float* sc2 = sm + 16384;      // 64
    float* sh2 = sm + 16448;      // 64
    float* sc3 = sm + 16512;      // 256
    float* sh3 = sm + 16768;      // 256
    int t = threadIdx.x;
    for (int i = t; i < 16384; i += 256) {
        int c = i >> 6, j = i & 63;
        WT[i] = w3[j * 256 + c];
    }
    if (t < 64) { sc2[t] = g_scale[320 + t]; sh2[t] = g_shift[320 + t]; }
    for (int i = t; i < 256; i += 256) { sc3[i] = g_scale[384 + i]; sh3[i] = g_shift[384 + i]; }
    __syncthreads();

    int q = blockIdx.x * 256 + t;
    if (q >= 200000) return;
    long r0 = 4L * q;
    u64 x0[32], x1[32], x2[32], x3[32];
    {
        u64* xs[4] = {x0, x1, x2, x3};
#pragma unroll
        for (int rr = 0; rr < 4; rr++) {
            const float* rp = g_Y2 + (r0 + rr) * 64;
            u64* xp = xs[rr];
#pragma unroll
            for (int m = 0; m < 16; m++) {
                float4 v = *(const float4*)(rp + 4 * m);
                float4 s = *(const float4*)(sc2 + 4 * m);
                float4 h = *(const float4*)(sh2 + 4 * m);
                float a0 = fmaxf(fmaf(v.x, s.x, h.x), 0.f);
                float a1 = fmaxf(fmaf(v.y, s.y, h.y), 0.f);
                float a2 = fmaxf(fmaf(v.z, s.z, h.z), 0.f);
                float a3 = fmaxf(fmaf(v.w, s.w, h.w), 0.f);
                xp[2*m] = pack2(a0, a1); xp[2*m+1] = pack2(a2, a3);
            }
        }
    }
    float* op = out + r0 * 256;
#pragma unroll 1
    for (int c = 0; c < 256; c += 2) {
        float2 v0, v1, v2, v3;
        dot2x4(WT, x0, x1, x2, x3, c, v0, v1, v2, v3);
        float sx = sc3[c], sy = sc3[c + 1];
        float hx = sh3[c], hy = sh3[c + 1];
        float2 o;
        o = unpack2(*(u64*)(op + 0 * 256 + c));
        *(u64*)(op + 0 * 256 + c) = pack2(o.x + fmaxf(fmaf(v0.x, sx, hx), 0.f),
                                          o.y + fmaxf(fmaf(v0.y, sy, hy), 0.f));
        o = unpack2(*(u64*)(op + 1 * 256 + c));
        *(u64*)(op + 1 * 256 + c) = pack2(o.x + fmaxf(fmaf(v1.x, sx, hx), 0.f),
                                          o.y + fmaxf(fmaf(v1.y, sy, hy), 0.f));
        o = unpack2(*(u64*)(op + 2 * 256 + c));
        *(u64*)(op + 2 * 256 + c) = pack2(o.x + fmaxf(fmaf(v2.x, sx, hx), 0.f),
                                          o.y + fmaxf(fmaf(v2.y, sy, hy), 0.f));
        o = unpack2(*(u64*)(op + 3 * 256 + c));
        *(u64*)(op + 3 * 256 + c) = pack2(o.x + fmaxf(fmaf(v3.x, sx, hx), 0.f),
                                          o.y + fmaxf(fmaf(v3.y, sy, hy), 0.f));
    }
}

extern "C" void kernel_launch(void* const* d_in, const int* in_sizes, int n_in,
                              void* d_out, int out_size) {
    const float* feats = (const float*)d_in[0];
    const int*   nbrs  = (const int*)d_in[1];
    const float* w1  = (const float*)d_in[2];
    const float* g1  = (const float*)d_in[4];
    const float* be1 = (const float*)d_in[5];
    const float* w2  = (const float*)d_in[6];
    const float* b2  = (const float*)d_in[7];
    const float* g2  = (const float*)d_in[8];
    const float* be2 = (const float*)d_in[9];
    const float* w3  = (const float*)d_in[10];
    const float* g3  = (const float*)d_in[12];
    const float* be3 = (const float*)d_in[13];
    const float* wsp = (const float*)d_in[14];
    const float* gsp = (const float*)d_in[16];
    const float* besp= (const float*)d_in[17];
    float* out = (float*)d_out;

    cudaFuncSetAttribute(gemm1_kernel, cudaFuncAttributeMaxDynamicSharedMemorySize, 84480);
    cudaFuncSetAttribute(gemm3_kernel, cudaFuncAttributeMaxDynamicSharedMemorySize, 68096);

    zero_kernel<<<16, 256>>>(0);                               // 0
    syrk_kernel<<<250, 256>>>(feats, 0);                       // 1
    prep_dual_kernel<<<2, 256>>>(w1, g1, be1, wsp, gsp, besp); // 2
    gemm1_kernel<<<782, 256, 84480>>>(feats, w1, wsp, out);    // 3  <- ncu slot
    compact_kernel<<<3125, 256>>>(nbrs);                       // 4
    conv_center_kernel<<<782, 256, 16640>>>(w2, b2);           // 5
    for (int kk = 0; kk < 8; kk++)
        convk_kernel<<<592, 256, 16384>>>(w2, kk);             // 6..13
    stats2_kernel<<<1184, 256>>>();                            // 14
    finalize2_kernel<<<1, 64>>>(g2, be2);                      // 15
    zero_kernel<<<16, 256>>>(1);                               // 16
    syrk_kernel<<<250, 256>>>(nullptr, 1);                     // 17
    prep_kernel<<<1, 256>>>(w3, g3, be3, 256, 384);            // 18
    gemm3_kernel<<<782, 256, 68096>>>(w3, out);                // 19
}

// round 16
// speedup vs baseline: 2.4308x; 2.4308x over previous
#include <cuda_runtime.h>

#define NP 800000
#define EPS 1e-5f
typedef unsigned long long u64;

// ---------------- global scratch ----------------
__device__ __align__(16) float g_h1[(size_t)NP * 64];    // stage-1 POST bn+relu
__device__ __align__(16) float g_Y2[(size_t)NP * 64];    // conv pre-BN (raw)
__device__ __align__(16) int2  g_list[8][NP];            // per-offset compacted (out, src)
__device__ __align__(16) int   g_cnt[8];
__device__ __align__(16) float g_stats[128];             // Y2: sum[0,64) sq[64,128)
__device__ __align__(16) float g_C[4096];                // 64x64 second-moment (raw sums)
__device__ __align__(16) float g_Csum[64];               // column sums
// scale/shift: Y1 @0..64, YS @64..320, h2 @320..384, Y3 @384..640
__device__ __align__(16) float g_scale[640];
__device__ __align__(16) float g_shift[640];

// ---------------- f32x2 helpers ----------------
__device__ __forceinline__ void ffma2(u64 &acc, u64 x, u64 w) {
    asm("fma.rn.f32x2 %0, %1, %2, %0;" : "+l"(acc) : "l"(x), "l"(w));
}
__device__ __forceinline__ u64 pack2(float a, float b) {
    u64 r; asm("mov.b64 %0, {%1, %2};" : "=l"(r)
               : "r"(__float_as_uint(a)), "r"(__float_as_uint(b))); return r;
}
__device__ __forceinline__ u64 dup2(float v) {
    u64 r; asm("mov.b64 %0, {%1, %1};" : "=l"(r) : "r"(__float_as_uint(v))); return r;
}
__device__ __forceinline__ float2 unpack2(u64 v) {
    unsigned lo, hi; asm("mov.b64 {%0, %1}, %2;" : "=r"(lo), "=r"(hi) : "l"(v));
    return make_float2(__uint_as_float(lo), __uint_as_float(hi));
}
__device__ __forceinline__ void load_row(const float* __restrict__ row, u64* xp) {
    const ulonglong2* xr = (const ulonglong2*)row;
#pragma unroll
    for (int m = 0; m < 16; m++) { ulonglong2 v = xr[m]; xp[2*m] = v.x; xp[2*m+1] = v.y; }
}

// ---- dot4x2 (2 rows x 4 cols) for the gather taps (proven R6 path) ----
__device__ __forceinline__ void dot4x2(const float* __restrict__ WT,
                                       const u64* __restrict__ xa, const u64* __restrict__ xb,
                                       int c, float4& ra, float4& rb) {
    const ulonglong2* w0 = (const ulonglong2*)(WT + (c + 0) * 64);
    const ulonglong2* w1 = (const ulonglong2*)(WT + (c + 1) * 64);
    const ulonglong2* w2 = (const ulonglong2*)(WT + (c + 2) * 64);
    const ulonglong2* w3 = (const ulonglong2*)(WT + (c + 3) * 64);
    u64 a0 = 0, a1 = 0, a2 = 0, a3 = 0;
    u64 b0 = 0, b1 = 0, b2 = 0, b3 = 0;
#pragma unroll
    for (int m = 0; m < 16; m++) {
        ulonglong2 v0 = w0[m];
        ffma2(a0, xa[2*m], v0.x); ffma2(a0, xa[2*m+1], v0.y);
        ffma2(b0, xb[2*m], v0.x); ffma2(b0, xb[2*m+1], v0.y);
        ulonglong2 v1 = w1[m];
        ffma2(a1, xa[2*m], v1.x); ffma2(a1, xa[2*m+1], v1.y);
        ffma2(b1, xb[2*m], v1.x); ffma2(b1, xb[2*m+1], v1.y);
        ulonglong2 v2 = w2[m];
        ffma2(a2, xa[2*m], v2.x); ffma2(a2, xa[2*m+1], v2.y);
        ffma2(b2, xb[2*m], v2.x); ffma2(b2, xb[2*m+1], v2.y);
        ulonglong2 v3 = w3[m];
        ffma2(a3, xa[2*m], v3.x); ffma2(a3, xa[2*m+1], v3.y);
        ffma2(b3, xb[2*m], v3.x); ffma2(b3, xb[2*m+1], v3.y);
    }
    float2 p;
    p = unpack2(a0); ra.x = p.x + p.y;
    p = unpack2(a1); ra.y = p.x + p.y;
    p = unpack2(a2); ra.z = p.x + p.y;
    p = unpack2(a3); ra.w = p.x + p.y;
    p = unpack2(b0); rb.x = p.x + p.y;
    p = unpack2(b1); rb.y = p.x + p.y;
    p = unpack2(b2); rb.z = p.x + p.y;
    p = unpack2(b3); rb.w = p.x + p.y;
}

__global__ void zero_kernel(int mode) {
    int i = blockIdx.x * blockDim.x + threadIdx.x;
    if (i < 4096) g_C[i] = 0.f;
    if (i < 64) g_Csum[i] = 0.f;
    if (mode == 0) {
        if (i < 128) g_stats[i] = 0.f;
        if (i < 8) g_cnt[i] = 0;
    }
}

// ---------------- SYRK: C += X^T X, Csum += colsums(X) ----------------
__global__ __launch_bounds__(256) void syrk_kernel(const float* __restrict__ Xin, int which) {
    __shared__ float tile[32 * 64];
    __shared__ float sc[64], sh[64];
    int t = threadIdx.x;
    if (which && t < 64) { sc[t] = g_scale[320 + t]; sh[t] = g_shift[320 + t]; }
    int ta = t >> 4, tb = t & 15;
    u64 acc[8] = {0,0,0,0,0,0,0,0};
    float cs0 = 0.f, cs1 = 0.f, cs2 = 0.f, cs3 = 0.f;
    const float4* src = (const float4*)(which ? (const float*)g_Y2 : Xin);
    long base16 = (long)blockIdx.x * 3200 * 16;

    for (int t0 = 0; t0 < 3200; t0 += 32) {
        __syncthreads();
        for (int i = t; i < 512; i += 256) {
            float4 v = src[base16 + (long)t0 * 16 + i];
            if (which) {
                int c0 = (i & 15) * 4;
                float4 s = *(const float4*)(sc + c0);
                float4 h = *(const float4*)(sh + c0);
                v.x = fmaxf(fmaf(v.x, s.x, h.x), 0.f);
                v.y = fmaxf(fmaf(v.y, s.y, h.y), 0.f);
                v.z = fmaxf(fmaf(v.z, s.z, h.z), 0.f);
                v.w = fmaxf(fmaf(v.w, s.w, h.w), 0.f);
            }
            *(float4*)(tile + i * 4) = v;
        }
        __syncthreads();
#pragma unroll 4
        for (int r = 0; r < 32; r++) {
            float4 xa = *(const float4*)(tile + r * 64 + ta * 4);
            float4 xb = *(const float4*)(tile + r * 64 + tb * 4);
            u64 b01 = pack2(xb.x, xb.y), b23 = pack2(xb.z, xb.w);
            u64 d;
            d = dup2(xa.x); ffma2(acc[0], d, b01); ffma2(acc[1], d, b23);
            d = dup2(xa.y); ffma2(acc[2], d, b01); ffma2(acc[3], d, b23);
            d = dup2(xa.z); ffma2(acc[4], d, b01); ffma2(acc[5], d, b23);
            d = dup2(xa.w); ffma2(acc[6], d, b01); ffma2(acc[7], d, b23);
            if (tb == 0) { cs0 += xa.x; cs1 += xa.y; cs2 += xa.z; cs3 += xa.w; }
        }
    }
#pragma unroll
    for (int a = 0; a < 4; a++) {
        float2 p0 = unpack2(acc[a * 2]), p1 = unpack2(acc[a * 2 + 1]);
        int row = ta * 4 + a;
        atomicAdd(&g_C[row * 64 + tb * 4 + 0], p0.x);
        atomicAdd(&g_C[row * 64 + tb * 4 + 1], p0.y);
        atomicAdd(&g_C[row * 64 + tb * 4 + 2], p1.x);
        atomicAdd(&g_C[row * 64 + tb * 4 + 3], p1.y);
    }
    if (tb == 0) {
        atomicAdd(&g_Csum[ta * 4 + 0], cs0);
        atomicAdd(&g_Csum[ta * 4 + 1], cs1);
        atomicAdd(&g_Csum[ta * 4 + 2], cs2);
        atomicAdd(&g_Csum[ta * 4 + 3], cs3);
    }
}

// ---------------- analytic BN params for y = x@W + b ----------------
__device__ __forceinline__ void prep_body(const float* __restrict__ W,
        const float* __restrict__ gamma, const float* __restrict__ beta,
        int ncols, int outOff) {
    __shared__ float Cs[4096];
    __shared__ float m[64];
    int t = threadIdx.x;
    float invN = 1.0f / (float)NP;
    for (int i = t; i < 4096; i += blockDim.x) Cs[i] = g_C[i] * invN;
    if (t < 64) m[t] = g_Csum[t] * invN;
    __syncthreads();
    if (t < ncols) {
        float w[64];
#pragma unroll
        for (int a = 0; a < 64; a++) w[a] = W[a * ncols + t];
        float mu = 0.f;
#pragma unroll
        for (int a = 0; a < 64; a++) mu = fmaf(m[a], w[a], mu);
        float q = 0.f;
#pragma unroll
        for (int a = 0; a < 64; a++) {
            const float* Cr = Cs + a * 64;
            float d0 = 0.f, d1 = 0.f, d2 = 0.f, d3 = 0.f;
#pragma unroll
            for (int b = 0; b < 64; b += 4) {
                d0 = fmaf(Cr[b + 0], w[b + 0], d0);
                d1 = fmaf(Cr[b + 1], w[b + 1], d1);
                d2 = fmaf(Cr[b + 2], w[b + 2], d2);
                d3 = fmaf(Cr[b + 3], w[b + 3], d3);
            }
            q = fmaf(w[a], (d0 + d1) + (d2 + d3), q);
        }
        float var = q - mu * mu;
        float scv = rsqrtf(var + EPS) * gamma[t];
        g_scale[outOff + t] = scv;
        g_shift[outOff + t] = beta[t] - mu * scv;
    }
}
__global__ void prep_dual_kernel(const float* __restrict__ w1, const float* __restrict__ g1,
                                 const float* __restrict__ be1,
                                 const float* __restrict__ ws, const float* __restrict__ gs,
                                 const float* __restrict__ bes) {
    if (blockIdx.x == 0) prep_body(w1, g1, be1, 64, 0);
    else                 prep_body(ws, gs, bes, 256, 64);
}
__global__ void prep_kernel(const float* __restrict__ W, const float* __restrict__ gamma,
                            const float* __restrict__ beta, int ncols, int outOff) {
    prep_body(W, gamma, beta, ncols, outOff);
}

// ================= tiled register-blocked GEMM core (8 rows x 8 cols per lane) =================
// xs layout: [k][256 rows] (stride 256 floats). ws layout per k-row (stride NC floats):
//   [coltile ct][h(2)][lcg(8)][pos(4)] where col = ct*64 + lcg*8 + h*4 + pos.
// Per k: 2x LDS.128 x-rowpairs + 2x LDS.128 w + 8 dup + 32 ffma2 -> 1:1 crossbar:fma.
#define TILE_KLOOP(ACC, XS, WS_LANE)                                              \
    _Pragma("unroll 8")                                                            \
    for (int k = 0; k < 64; k++) {                                                 \
        const float* xr = (XS) + k * 256 + R0;                                     \
        ulonglong2 xa = *(const ulonglong2*)xr;                                    \
        ulonglong2 xb = *(const ulonglong2*)(xr + 4);                              \
        const float* wr = (WS_LANE) + k * WSTRIDE;                                 \
        float4 wv0 = *(const float4*)wr;                                           \
        float4 wv1 = *(const float4*)(wr + 32);                                    \
        u64 d;                                                                     \
        d = dup2(wv0.x); ffma2(ACC[0], xa.x, d); ffma2(ACC[8],  xa.y, d);          \
                         ffma2(ACC[16], xb.x, d); ffma2(ACC[24], xb.y, d);         \
        d = dup2(wv0.y); ffma2(ACC[1], xa.x, d); ffma2(ACC[9],  xa.y, d);          \
                         ffma2(ACC[17], xb.x, d); ffma2(ACC[25], xb.y, d);         \
        d = dup2(wv0.z); ffma2(ACC[2], xa.x, d); ffma2(ACC[10], xa.y, d);          \
                         ffma2(ACC[18], xb.x, d); ffma2(ACC[26], xb.y, d);         \
        d = dup2(wv0.w); ffma2(ACC[3], xa.x, d); ffma2(ACC[11], xa.y, d);          \
                         ffma2(ACC[19], xb.x, d); ffma2(ACC[27], xb.y, d);         \
        d = dup2(wv1.x); ffma2(ACC[4], xa.x, d); ffma2(ACC[12], xa.y, d);          \
                         ffma2(ACC[20], xb.x, d); ffma2(ACC[28], xb.y, d);         \
        d = dup2(wv1.y); ffma2(ACC[5], xa.x, d); ffma2(ACC[13], xa.y, d);          \
                         ffma2(ACC[21], xb.x, d); ffma2(ACC[29], xb.y, d);         \
        d = dup2(wv1.z); ffma2(ACC[6], xa.x, d); ffma2(ACC[14], xa.y, d);          \
                         ffma2(ACC[22], xb.x, d); ffma2(ACC[30], xb.y, d);         \
        d = dup2(wv1.w); ffma2(ACC[7], xa.x, d); ffma2(ACC[15], xa.y, d);          \
                         ffma2(ACC[23], xb.x, d); ffma2(ACC[31], xb.y, d);         \
    }
// acc[rp*8 + j]: rowpair rp (rows R0+2rp, R0+2rp+1), lane col j (global col = ct*64+lcg*8 + perm(j))
// perm: j 0..3 -> +h0 cols (lcg*8 + 0..3)? NO: with layout [h][lcg][pos], wv0 = cols lcg*8+{0,1,2,3}
// only if h indexes upper half: col = ct*64 + lcg*8 + h*4 + pos, wv0 (h=0) = lcg*8+0..3, wv1 (h=1) = +4..7. ✓

// permuted ws staging: given col c (0..NC-1) value v, store at k-row offset
__device__ __forceinline__ int ws_perm(int c) {
    int ct = c >> 6, cc = c & 63;
    int lcg = (cc >> 3), h = (cc >> 2) & 1, pos = cc & 3;
    return ct * 64 + h * 32 + lcg * 4 + pos;
}

// ---------------- GEMM1 tiled: h1 = relu(bn(feats@w1)); out = bn(feats@ws) ----------------
#define WSTRIDE 320
__global__ __launch_bounds__(256, 1) void gemm1_kernel(
    const float* __restrict__ feats, const float* __restrict__ w1,
    const float* __restrict__ wsp, float* __restrict__ outYS) {
    extern __shared__ float sm[];
    float* xs = sm;               // 64 x 256
    float* ws = sm + 16384;       // 64 x 320 permuted
    float* scA = sm + 36864;      // 320
    float* shA = sm + 37184;      // 320
    int t = threadIdx.x;
    long rowbase = (long)blockIdx.x * 256;
    {   // stage x transposed: thread owns row rowbase + t
        const float4* src = (const float4*)(feats + (rowbase + t) * 64);
#pragma unroll
        for (int m = 0; m < 16; m++) {
            float4 v = src[m];
            xs[(4*m+0)*256 + t] = v.x;
            xs[(4*m+1)*256 + t] = v.y;
            xs[(4*m+2)*256 + t] = v.z;
            xs[(4*m+3)*256 + t] = v.w;
        }
    }
    for (int i = t; i < 20480; i += 256) {
        int k = i / 320, c = i - k * 320;
        float v = (c < 64) ? w1[k * 64 + c] : wsp[k * 256 + (c - 64)];
        ws[k * 320 + ws_perm(c)] = v;
    }
    for (int i = t; i < 320; i += 256) { scA[i] = g_scale[i]; shA[i] = g_shift[i]; }
    __syncthreads();

    int w = t >> 5, lane = t & 31;
    int lrg = lane >> 3, lcg = lane & 7;
    int R0 = w * 32 + lrg * 8;
    const float* wlane = ws + lcg * 4;
#pragma unroll 1
    for (int ct = 0; ct < 5; ct++) {
        u64 acc[32];
#pragma unroll
        for (int i = 0; i < 32; i++) acc[i] = 0;
        const float* wl = wlane + ct * 64;
        TILE_KLOOP(acc, xs, wl)
        int cbase = ct * 64 + lcg * 8;
        float sc[8], sh[8];
#pragma unroll
        for (int j = 0; j < 8; j++) { sc[j] = scA[cbase + j]; sh[j] = shA[cbase + j]; }
#pragma unroll
        for (int rp = 0; rp < 4; rp++) {
            long r0g = rowbase + R0 + 2 * rp;
            float v0[8], v1[8];
#pragma unroll
            for (int j = 0; j < 8; j++) {
                float2 p = unpack2(acc[rp * 8 + j]);
                v0[j] = fmaf(p.x, sc[j], sh[j]);
                v1[j] = fmaf(p.y, sc[j], sh[j]);
            }
            if (ct == 0) {
#pragma unroll
                for (int j = 0; j < 8; j++) { v0[j] = fmaxf(v0[j], 0.f); v1[j] = fmaxf(v1[j], 0.f); }
                float* p0 = g_h1 + r0g * 64 + cbase;
                *(float4*)p0 = make_float4(v0[0], v0[1], v0[2], v0[3]);
                *(float4*)(p0 + 4) = make_float4(v0[4], v0[5], v0[6], v0[7]);
                float* p1 = p0 + 64;
                *(float4*)p1 = make_float4(v1[0], v1[1], v1[2], v1[3]);
                *(float4*)(p1 + 4) = make_float4(v1[4], v1[5], v1[6], v1[7]);
            } else {
                float* p0 = outYS + r0g * 256 + (cbase - 64);
                *(float4*)p0 = make_float4(v0[0], v0[1], v0[2], v0[3]);
                *(float4*)(p0 + 4) = make_float4(v0[4], v0[5], v0[6], v0[7]);
                float* p1 = p0 + 256;
                *(float4*)p1 = make_float4(v1[0], v1[1], v1[2], v1[3]);
                *(float4*)(p1 + 4) = make_float4(v1[4], v1[5], v1[6], v1[7]);
            }
        }
    }
}
#undef WSTRIDE

// ---------------- conv center tiled: Y2 = b2 + h1 @ w2[4] ----------------
#define WSTRIDE 64
__global__ __launch_bounds__(256, 1) void conv_center_kernel(
    const float* __restrict__ w2, const float* __restrict__ b2) {
    extern __shared__ float sm[];
    float* xs = sm;              // 64 x 256
    float* ws = sm + 16384;      // 64 x 64 permuted
    float* bias = sm + 20480;    // 64
    int t = threadIdx.x;
    long rowbase = (long)blockIdx.x * 256;
    {
        const float4* src = (const float4*)(g_h1 + (rowbase + t) * 64);
#pragma unroll
        for (int m = 0; m < 16; m++) {
            float4 v = src[m];
            xs[(4*m+0)*256 + t] = v.x;
            xs[(4*m+1)*256 + t] = v.y;
            xs[(4*m+2)*256 + t] = v.z;
            xs[(4*m+3)*256 + t] = v.w;
        }
    }
    for (int i = t; i < 4096; i += 256) {
        int k = i >> 6, c = i & 63;
        ws[k * 64 + ws_perm(c)] = w2[4 * 4096 + k * 64 + c];
    }
    if (t < 64) bias[t] = b2[t];
    __syncthreads();

    int w = t >> 5, lane = t & 31;
    int lrg = lane >> 3, lcg = lane & 7;
    int R0 = w * 32 + lrg * 8;
    u64 acc[32];
#pragma unroll
    for (int i = 0; i < 32; i++) acc[i] = 0;
    const float* wl = ws + lcg * 4;
    TILE_KLOOP(acc, xs, wl)
    int cbase = lcg * 8;
    float bv[8];
#pragma unroll
    for (int j = 0; j < 8; j++) bv[j] = bias[cbase + j];
#pragma unroll
    for (int rp = 0; rp < 4; rp++) {
        long r0g = rowbase + R0 + 2 * rp;
        float v0[8], v1[8];
#pragma unroll
        for (int j = 0; j < 8; j++) {
            float2 p = unpack2(acc[rp * 8 + j]);
            v0[j] = p.x + bv[j];
            v1[j] = p.y + bv[j];
        }
        float* p0 = g_Y2 + r0g * 64 + cbase;
        *(float4*)p0 = make_float4(v0[0], v0[1], v0[2], v0[3]);
        *(float4*)(p0 + 4) = make_float4(v0[4], v0[5], v0[6], v0[7]);
        float* p1 = p0 + 64;
        *(float4*)p1 = make_float4(v1[0], v1[1], v1[2], v1[3]);
        *(float4*)(p1 + 4) = make_float4(v1[4], v1[5], v1[6], v1[7]);
    }
}
#undef WSTRIDE

// ---------------- GEMM3 tiled: out += relu(bn(bnrelu(Y2) @ w3)) ----------------
#define WSTRIDE 256
__global__ __launch_bounds__(256, 1) void gemm3_kernel(
    const float* __restrict__ w3, float* __restrict__ out) {
    extern __shared__ float sm[];
    float* xs = sm;              // 64 x 256
    float* ws = sm + 16384;      // 64 x 256 permuted
    float* sc3 = sm + 32768;     // 256
    float* sh3 = sm + 33024;     // 256
    int t = threadIdx.x;
    long rowbase = (long)blockIdx.x * 256;
    {   // stage x with bnrelu applied (scales read from global; broadcast L1 hits)
        const float4* src = (const float4*)(g_Y2 + (rowbase + t) * 64);
#pragma unroll
        for (int m = 0; m < 16; m++) {
            float4 v = src[m];
            float4 s = *(const float4*)(g_scale + 320 + 4 * m);
            float4 h = *(const float4*)(g_shift + 320 + 4 * m);
            xs[(4*m+0)*256 + t] = fmaxf(fmaf(v.x, s.x, h.x), 0.f);
            xs[(4*m+1)*256 + t] = fmaxf(fmaf(v.y, s.y, h.y), 0.f);
            xs[(4*m+2)*256 + t] = fmaxf(fmaf(v.z, s.z, h.z), 0.f);
            xs[(4*m+3)*256 + t] = fmaxf(fmaf(v.w, s.w, h.w), 0.f);
        }
    }
    for (int i = t; i < 16384; i += 256) {
        int k = i >> 8, c = i & 255;
        ws[k * 256 + ws_perm(c)] = w3[k * 256 + c];
    }
    if (t < 256) { sc3[t] = g_scale[384 + t]; sh3[t] = g_shift[384 + t]; }
    __syncthreads();

    int w = t >> 5, lane = t & 31;
    int lrg = lane >> 3, lcg = lane & 7;
    int R0 = w * 32 + lrg * 8;
    const float* wlane = ws + lcg * 4;
#pragma unroll 1
    for (int ct = 0; ct < 4; ct++) {
        u64 acc[32];
#pragma unroll
        for (int i = 0; i < 32; i++) acc[i] = 0;
        const float* wl = wlane + ct * 64;
        TILE_KLOOP(acc, xs, wl)
        int cbase = ct * 64 + lcg * 8;
        float sc[8], sh[8];
#pragma unroll
        for (int j = 0; j < 8; j++) { sc[j] = sc3[cbase + j]; sh[j] = sh3[cbase + j]; }
#pragma unroll
        for (int rp = 0; rp < 4; rp++) {
            long r0g = rowbase + R0 + 2 * rp;
            float* p0 = out + r0g * 256 + cbase;
            float* p1 = p0 + 256;
            float4 oa = *(float4*)p0, ob = *(float4*)(p0 + 4);
            float4 oc = *(float4*)p1, od = *(float4*)(p1 + 4);
            float2 p;
            p = unpack2(acc[rp*8+0]); oa.x += fmaxf(fmaf(p.x, sc[0], sh[0]), 0.f); oc.x += fmaxf(fmaf(p.y, sc[0], sh[0]), 0.f);
            p = unpack2(acc[rp*8+1]); oa.y += fmaxf(fmaf(p.x, sc[1], sh[1]), 0.f); oc.y += fmaxf(fmaf(p.y, sc[1], sh[1]), 0.f);
            p = unpack2(acc[rp*8+2]); oa.z += fmaxf(fmaf(p.x, sc[2], sh[2]), 0.f); oc.z += fmaxf(fmaf(p.y, sc[2], sh[2]), 0.f);
            p = unpack2(acc[rp*8+3]); oa.w += fmaxf(fmaf(p.x, sc[3], sh[3]), 0.f); oc.w += fmaxf(fmaf(p.y, sc[3], sh[3]), 0.f);
            p = unpack2(acc[rp*8+4]); ob.x += fmaxf(fmaf(p.x, sc[4], sh[4]), 0.f); od.x += fmaxf(fmaf(p.y, sc[4], sh[4]), 0.f);
            p = unpack2(acc[rp*8+5]); ob.y += fmaxf(fmaf(p.x, sc[5], sh[5]), 0.f); od.y += fmaxf(fmaf(p.y, sc[5], sh[5]), 0.f);
            p = unpack2(acc[rp*8+6]); ob.z += fmaxf(fmaf(p.x, sc[6], sh[6]), 0.f); od.z += fmaxf(fmaf(p.y, sc[6], sh[6]), 0.f);
            p = unpack2(acc[rp*8+7]); ob.w += fmaxf(fmaf(p.x, sc[7], sh[7]), 0.f); od.w += fmaxf(fmaf(p.y, sc[7], sh[7]), 0.f);
            *(float4*)p0 = oa; *(float4*)(p0 + 4) = ob;
            *(float4*)p1 = oc; *(float4*)(p1 + 4) = od;
        }
    }
}
#undef WSTRIDE

// ---------------- direct column stats for Y2 ----------------
__global__ __launch_bounds__(256) void stats2_kernel() {
    __shared__ float s[128];
    int t = threadIdx.x;
    for (int i = t; i < 128; i += 256) s[i] = 0.f;
    __syncthreads();
    int cg = t & 15;
    long r = (long)blockIdx.x * 16 + (t >> 4);
    long stride = (long)gridDim.x * 16;
    float s0=0,s1=0,s2=0,s3=0,q0=0,q1=0,q2=0,q3=0;
    for (; r < NP; r += stride) {
        float4 v = *(const float4*)(g_Y2 + r * 64 + cg * 4);
        s0 += v.x; q0 = fmaf(v.x, v.x, q0);
        s1 += v.y; q1 = fmaf(v.y, v.y, q1);
        s2 += v.z; q2 = fmaf(v.z, v.z, q2);
        s3 += v.w; q3 = fmaf(v.w, v.w, q3);
    }
    int c = cg * 4;
    atomicAdd(&s[c+0], s0); atomicAdd(&s[c+1], s1);
    atomicAdd(&s[c+2], s2); atomicAdd(&s[c+3], s3);
    atomicAdd(&s[64+c+0], q0); atomicAdd(&s[64+c+1], q1);
    atomicAdd(&s[64+c+2], q2); atomicAdd(&s[64+c+3], q3);
    __syncthreads();
    for (int i = t; i < 128; i += 256) atomicAdd(&g_stats[i], s[i]);
}
__global__ void finalize2_kernel(const float* __restrict__ gamma, const float* __restrict__ beta) {
    int t = threadIdx.x;
    if (t < 64) {
        float inv = 1.0f / (float)NP;
        float m = g_stats[t] * inv;
        float v = g_stats[64 + t] * inv - m * m;
        float sc = rsqrtf(v + EPS) * gamma[t];
        g_scale[320 + t] = sc;
        g_shift[320 + t] = beta[t] - m * sc;
    }
}

// ---------------- compaction ----------------
__global__ __launch_bounds__(256) void compact_kernel(const int* __restrict__ nbrs) {
    __shared__ int scnt[8], sbase[8], woff[8][8];
    int t = threadIdx.x, w = t >> 5, lane = t & 31;
    if (t < 8) scnt[t] = 0;
    __syncthreads();
    int i = blockIdx.x * 256 + t;
    int nb[8];
    {
        int kk = 0;
#pragma unroll
        for (int k = 0; k < 9; k++) {
            if (k == 4) continue;
            nb[kk++] = nbrs[i * 9 + k];
        }
    }
    unsigned ball[8];
#pragma unroll
    for (int k = 0; k < 8; k++) {
        unsigned m = __ballot_sync(0xffffffffu, nb[k] >= 0);
        ball[k] = m;
        if (lane == 0) woff[k][w] = atomicAdd(&scnt[k], __popc(m));
    }
    __syncthreads();
    if (t < 8) sbase[t] = atomicAdd(&g_cnt[t], scnt[t]);
    __syncthreads();
#pragma unroll
    for (int k = 0; k < 8; k++) {
        if (nb[k] >= 0) {
            int r = __popc(ball[k] & ((1u << lane) - 1u));
            g_list[k][sbase[k] + woff[k][w] + r] = make_int2(i, nb[k]);
        }
    }
}

// ---------------- conv non-center tap kk (R6 proven: 2 entries/thread) ----------------
__global__ __launch_bounds__(256, 1) void convk_kernel(const float* __restrict__ w2, int kk) {
    extern __shared__ float sm[];
    float* WT = sm;
    int tap = (kk < 4) ? kk : kk + 1;
    int t = threadIdx.x;
    for (int i = t; i < 4096; i += 256) {
        int c = i >> 6, j = i & 63;
        WT[i] = w2[tap * 4096 + j * 64 + c];
    }
    __syncthreads();

    int n = g_cnt[kk];
    for (long e = ((long)blockIdx.x * 256 + t) * 2; e < n; e += (long)gridDim.x * 512) {
        int2 e0 = g_list[kk][e];
        bool two = (e + 1 < n);
        int2 e1 = two ? g_list[kk][e + 1] : e0;
        u64 xa[32], xb[32];
        load_row(g_h1 + (long)e0.y * 64, xa);
        load_row(g_h1 + (long)e1.y * 64, xb);
        float* ya = g_Y2 + (long)e0.x * 64;
        float* yb = g_Y2 + (long)e1.x * 64;
#pragma unroll 1
        for (int cq = 0; cq < 16; cq++) {
            int c = cq * 4;
            float4 ra, rb;
            dot4x2(WT, xa, xb, c, ra, rb);
            float4 y0 = *(float4*)(ya + c);
            y0.x += ra.x; y0.y += ra.y; y0.z += ra.z; y0.w += ra.w;
            *(float4*)(ya + c) = y0;
            if (two) {
                float4 y1 = *(float4*)(yb + c);
                y1.x += rb.x; y1.y += rb.y; y1.z += rb.z; y1.w += rb.w;
                *(float4*)(yb + c) = y1;
            }
        }
    }
}

extern "C" void kernel_launch(void* const* d_in, const int* in_sizes, int n_in,
                              void* d_out, int out_size) {
    const float* feats = (const float*)d_in[0];
    const int*   nbrs  = (const int*)d_in[1];
    const float* w1  = (const float*)d_in[2];
    const float* g1  = (const float*)d_in[4];
    const float* be1 = (const float*)d_in[5];
    const float* w2  = (const float*)d_in[6];
    const float* b2  = (const float*)d_in[7];
    const float* g2  = (const float*)d_in[8];
    const float* be2 = (const float*)d_in[9];
    const float* w3  = (const float*)d_in[10];
    const float* g3  = (const float*)d_in[12];
    const float* be3 = (const float*)d_in[13];
    const float* wsp = (const float*)d_in[14];
    const float* gsp = (const float*)d_in[16];
    const float* besp= (const float*)d_in[17];
    float* out = (float*)d_out;

    cudaFuncSetAttribute(gemm1_kernel, cudaFuncAttributeMaxDynamicSharedMemorySize, 150016);
    cudaFuncSetAttribute(gemm3_kernel, cudaFuncAttributeMaxDynamicSharedMemorySize, 133120);
    cudaFuncSetAttribute(conv_center_kernel, cudaFuncAttributeMaxDynamicSharedMemorySize, 82176);

    zero_kernel<<<16, 256>>>(0);                               // 0
    syrk_kernel<<<250, 256>>>(feats, 0);                       // 1
    prep_dual_kernel<<<2, 256>>>(w1, g1, be1, wsp, gsp, besp); // 2
    gemm1_kernel<<<3125, 256, 150016>>>(feats, w1, wsp, out);  // 3  <- ncu slot
    compact_kernel<<<3125, 256>>>(nbrs);                       // 4
    conv_center_kernel<<<3125, 256, 82176>>>(w2, b2);          // 5
    for (int kk = 0; kk < 8; kk++)
        convk_kernel<<<592, 256, 16384>>>(w2, kk);             // 6..13
    stats2_kernel<<<1184, 256>>>();                            // 14
    finalize2_kernel<<<1, 64>>>(g2, be2);                      // 15
    zero_kernel<<<16, 256>>>(1);                               // 16
    syrk_kernel<<<250, 256>>>(nullptr, 1);                     // 17
    prep_kernel<<<1, 256>>>(w3, g3, be3, 256, 384);            // 18
    gemm3_kernel<<<3125, 256, 133120>>>(w3, out);              // 19
}